// round 7
// baseline (speedup 1.0000x reference)
#include <cuda_runtime.h>
#include <math.h>

// x: [B=2, T=64, C=16, H=128, W=128] f32; qkv conv 3x3 pad1 (16->16),
// nh=8, hc=2, D=32768; causal softmax T=64; out conv 3x3 (16->16).
#define HW 16384
typedef unsigned long long ull;

// ---------------- packed fp32x2 helpers (FFMA2 path, 2x fp32 tput) --------
__device__ __forceinline__ ull pk2(float lo, float hi) {
    ull r;
    asm("mov.b64 %0, {%1, %2};"
        : "=l"(r) : "r"(__float_as_uint(lo)), "r"(__float_as_uint(hi)));
    return r;
}
__device__ __forceinline__ void fma2(ull& d, ull a, ull b) {
    asm("fma.rn.f32x2 %0, %1, %2, %0;" : "+l"(d) : "l"(a), "l"(b));
}
__device__ __forceinline__ float2 upk(ull v) {
    unsigned lo, hi;
    asm("mov.b64 {%0, %1}, %2;" : "=r"(lo), "=r"(hi) : "l"(v));
    return make_float2(__uint_as_float(lo), __uint_as_float(hi));
}

// ---------------- scratch ----------------
__device__ float g_q[2*64*16*16384];   // q, later reused as attention output y
__device__ float g_k[2*64*16*16384];
__device__ float g_v[2*64*16*16384];
__device__ float g_part[64*16*64*64];  // QK^T partials per k-split
__device__ float g_att[16*64*64];      // softmax probs, [bh][s][t]

// ---------------- 3x3 conv, channel-pair FFMA2, dup-pixel smem -----------
// f32x2 lanes = two OUTPUT CHANNELS. Halo tile stored as (v,v) pairs so a
// tap pair is one aligned LDS.128 — no packing movs in the inner loop.
// Block 128 thr = 4 warps (channel groups) x 32 pixel slots; tile 32w x 4h,
// thread = 4 pixels x PPG channel-pairs.
template<int NCONV>
__global__ void __launch_bounds__(128) conv3x3_kernel(
    const float* __restrict__ xin,
    const float* __restrict__ w0, const float* __restrict__ b0,
    const float* __restrict__ w1, const float* __restrict__ b1,
    const float* __restrict__ w2, const float* __restrict__ b2,
    float* __restrict__ out_final)
{
    constexpr int NPAIR = NCONV * 8;     // channel pairs total
    constexpr int PPG   = NPAIR / 4;     // pairs per warp
    extern __shared__ ull dyn[];
    ull*   s_w2 = dyn;                          // NPAIR*16ic*10 packed (wA,wB)
    ull*   s_in = dyn + NPAIR*160;              // 16c x 6row x 36col dup pairs
    float* s_b  = (float*)(s_in + 16*216);      // NCONV*16 biases

    const int tid = threadIdx.x;
    const int bt  = blockIdx.y;                 // image 0..127
    const int th0 = (blockIdx.x >> 2) * 4;      // tile origin h
    const int tw0 = (blockIdx.x & 3) * 32;      // tile origin w

    const float* x = (NCONV == 3) ? xin : g_q;  // final conv reads y (on g_q)

    // stage weights as channel-pair packs: [(pair*16+ic)*10 + j] = (w[2p], w[2p+1])
    {
        const float* wsrc[3] = {w0, w1, w2};
        for (int idx = tid; idx < NPAIR*144; idx += 128) {
            int pair = idx / 144;
            int r    = idx - pair*144;          // ic*9 + j
            int chA  = pair*2, chB = chA + 1;
            float a  = wsrc[chA >> 4][(chA & 15)*144 + r];
            float b  = wsrc[chB >> 4][(chB & 15)*144 + r];
            int ic   = r / 9;
            int j    = r - ic*9;
            s_w2[(pair*16 + ic)*10 + j] = pk2(a, b);
        }
        for (int idx = tid; idx < NCONV*16; idx += 128) {
            float bv;
            if (NCONV == 3) bv = (idx < 16) ? b0[idx] : (idx < 32 ? b1[idx-16] : b2[idx-32]);
            else            bv = b0[idx];
            s_b[idx] = bv;
        }
    }

    // stage input tile with halo, duplicated (v,v): rows th0-1..th0+4,
    // cols tw0-1..tw0+32.  s_in[c*216 + yy*36 + xx] = (v,v)
    for (int idx = tid; idx < 16*6*34; idx += 128) {
        int c   = idx / 204;
        int rem = idx - c*204;
        int yy  = rem / 34;
        int xx  = rem - yy*34;
        int gh  = th0 + yy - 1;
        int gw  = tw0 + xx - 1;
        float v = 0.f;
        if (gh >= 0 && gh < 128 && gw >= 0 && gw < 128)
            v = x[((size_t)bt*16 + c)*HW + gh*128 + gw];
        s_in[c*216 + yy*36 + xx] = pk2(v, v);
    }
    __syncthreads();

    const int cg  = tid >> 5;           // warp = channel group (PPG pairs)
    const int sl  = tid & 31;           // pixel slot
    const int py  = sl >> 3;            // tile row 0..3
    const int x0  = (sl & 7) * 4;       // tile col start (even -> aligned)

    ull acc[PPG][4];
#pragma unroll
    for (int c = 0; c < PPG; ++c) {
        int q = cg*PPG + c;
        ull b2 = pk2(s_b[2*q], s_b[2*q + 1]);
#pragma unroll
        for (int p = 0; p < 4; ++p) acc[c][p] = b2;
    }

    const ull* Sp = s_in + py*36 + x0;
    for (int ic = 0; ic < 16; ++ic) {
        const ull* p0 = Sp + ic*216;
        ull e[3][6];
#pragma unroll
        for (int ky = 0; ky < 3; ++ky) {
            ulonglong2 pA = *(const ulonglong2*)(p0 + ky*36);
            ulonglong2 pB = *(const ulonglong2*)(p0 + ky*36 + 2);
            ulonglong2 pC = *(const ulonglong2*)(p0 + ky*36 + 4);
            e[ky][0] = pA.x; e[ky][1] = pA.y;
            e[ky][2] = pB.x; e[ky][3] = pB.y;
            e[ky][4] = pC.x; e[ky][5] = pC.y;
        }
#pragma unroll
        for (int c = 0; c < PPG; ++c) {
            const ull* wp = s_w2 + ((cg*PPG + c)*16 + ic)*10;
            ulonglong2 wA = *(const ulonglong2*)wp;        // taps 0,1
            ulonglong2 wB = *(const ulonglong2*)(wp + 2);  // taps 2,3
            ulonglong2 wC = *(const ulonglong2*)(wp + 4);  // taps 4,5
            ulonglong2 wD = *(const ulonglong2*)(wp + 6);  // taps 6,7
            ull w8 = wp[8];
#pragma unroll
            for (int px = 0; px < 4; ++px) {
                ull a = acc[c][px];
                fma2(a, e[0][px+0], wA.x);
                fma2(a, e[0][px+1], wA.y);
                fma2(a, e[0][px+2], wB.x);
                fma2(a, e[1][px+0], wB.y);
                fma2(a, e[1][px+1], wC.x);
                fma2(a, e[1][px+2], wC.y);
                fma2(a, e[2][px+0], wD.x);
                fma2(a, e[2][px+1], wD.y);
                fma2(a, e[2][px+2], w8);
                acc[c][px] = a;
            }
        }
    }

    const int oh = th0 + py;
    const int ow = tw0 + x0;
#pragma unroll
    for (int c = 0; c < PPG; ++c) {
        int q    = cg*PPG + c;
        int chA  = 2*q, chB = chA + 1;
        float2 v0 = upk(acc[c][0]);
        float2 v1 = upk(acc[c][1]);
        float2 v2 = upk(acc[c][2]);
        float2 v3 = upk(acc[c][3]);
        float* outA;
        float* outB;
        if (NCONV == 3) {
            outA = (chA < 16) ? g_q : (chA < 32 ? g_k : g_v);
            outB = (chB < 16) ? g_q : (chB < 32 ? g_k : g_v);
        } else {
            outA = out_final; outB = out_final;
        }
        size_t offA = ((size_t)bt*16 + (chA & 15))*HW + oh*128 + ow;
        size_t offB = ((size_t)bt*16 + (chB & 15))*HW + oh*128 + ow;
        *(float4*)(outA + offA) = make_float4(v0.x, v1.x, v2.x, v3.x);
        *(float4*)(outB + offB) = make_float4(v0.y, v1.y, v2.y, v3.y);
    }
}

// ---------------- QK^T with K-split, FFMA2 inner ----------------
__global__ void __launch_bounds__(256) qk_kernel()
{
    __shared__ __align__(16) float Qs[64][68];
    __shared__ __align__(16) float Ks[64][68];
    const int bh = blockIdx.y;
    const int b  = bh >> 3, h = bh & 7;
    const int split = blockIdx.x;
    const int tid = threadIdx.x;
    const int ty = tid >> 4, tx = tid & 15;

    ull acc2[4][2];
#pragma unroll
    for (int i = 0; i < 4; ++i) { acc2[i][0] = 0ULL; acc2[i][1] = 0ULL; }

    for (int sub = 0; sub < 8; ++sub) {
        const int kc = split*512 + sub*64;
        __syncthreads();
        for (int i = tid; i < 1024; i += 256) {
            int t  = i >> 4;
            int kq = (i & 15) << 2;
            size_t base = ((size_t)((b*64 + t)*16 + h*2))*HW + kc + kq;
            float4 qa = *(const float4*)(g_q + base);
            float4 ka = *(const float4*)(g_k + base);
            Qs[kq+0][t] = qa.x; Qs[kq+1][t] = qa.y; Qs[kq+2][t] = qa.z; Qs[kq+3][t] = qa.w;
            Ks[kq+0][t] = ka.x; Ks[kq+1][t] = ka.y; Ks[kq+2][t] = ka.z; Ks[kq+3][t] = ka.w;
        }
        __syncthreads();
#pragma unroll 8
        for (int kk = 0; kk < 64; ++kk) {
            float4 a = *(const float4*)&Qs[kk][ty*4];
            ulonglong2 bp = *(const ulonglong2*)&Ks[kk][tx*4];
            ull a0 = pk2(a.x, a.x);
            ull a1 = pk2(a.y, a.y);
            ull a2 = pk2(a.z, a.z);
            ull a3 = pk2(a.w, a.w);
            fma2(acc2[0][0], a0, bp.x); fma2(acc2[0][1], a0, bp.y);
            fma2(acc2[1][0], a1, bp.x); fma2(acc2[1][1], a1, bp.y);
            fma2(acc2[2][0], a2, bp.x); fma2(acc2[2][1], a2, bp.y);
            fma2(acc2[3][0], a3, bp.x); fma2(acc2[3][1], a3, bp.y);
        }
    }

    float* dst = g_part + ((size_t)(split*16 + bh))*4096;
#pragma unroll
    for (int i = 0; i < 4; ++i) {
        float2 lo = upk(acc2[i][0]);
        float2 hi = upk(acc2[i][1]);
        *(float4*)(dst + (ty*4 + i)*64 + tx*4) = make_float4(lo.x, lo.y, hi.x, hi.y);
    }
}

// ---------------- split-reduce + causal softmax ----------------
__global__ void softmax_kernel()
{
    const int bh = blockIdx.y;
    const int t  = blockIdx.x;
    const int s  = threadIdx.x;

    float ssum = 0.f;
    for (int sp = 0; sp < 64; ++sp)
        ssum += g_part[((size_t)(sp*16 + bh)*64 + t)*64 + s];

    const float scale = rsqrtf(32768.0f);
    const bool valid = (s <= t);
    float logit = valid ? ssum * scale : -INFINITY;

    __shared__ float red[64];
    red[s] = logit;
    __syncthreads();
    for (int off = 32; off > 0; off >>= 1) {
        if (s < off) red[s] = fmaxf(red[s], red[s + off]);
        __syncthreads();
    }
    float mx = red[0];
    __syncthreads();
    float e = valid ? expf(logit - mx) : 0.f;
    red[s] = e;
    __syncthreads();
    for (int off = 32; off > 0; off >>= 1) {
        if (s < off) red[s] += red[s + off];
        __syncthreads();
    }
    float p = e / red[0];
    g_att[(bh*64 + s)*64 + t] = p;   // 0 for s > t
}

// ---------------- y = att @ V: 2 d-cols per thread, causal split ----------
// grid (64, 2, 16), block 256; thread = 2 consecutive d, 32 t (16 packed pairs).
__global__ void __launch_bounds__(256) av_kernel()
{
    __shared__ __align__(16) float sa[64][32];   // att[s][t0+tt]
    const int bh = blockIdx.z;
    const int b  = bh >> 3, h = bh & 7;
    const int thalf = blockIdx.y;
    const int t0 = thalf * 32;
    const int smax = thalf ? 64 : 32;   // causal: lower t-half only needs s<32
    const int d0 = blockIdx.x*512 + threadIdx.x*2;

    for (int i = threadIdx.x; i < smax*8; i += 256) {
        int s = i >> 3; int tg = i & 7;
        *(float4*)&sa[s][tg*4] = *(const float4*)(g_att + (bh*64 + s)*64 + t0 + tg*4);
    }
    __syncthreads();

    ull acc[16][2];
#pragma unroll
    for (int g = 0; g < 16; ++g) { acc[g][0] = 0ULL; acc[g][1] = 0ULL; }

    const size_t vbase = ((size_t)(b*64*16 + h*2))*HW + d0;
#pragma unroll 2
    for (int s = 0; s < smax; ++s) {
        float2 v = *(const float2*)(g_v + vbase + (size_t)s*16*HW);
        ull va = pk2(v.x, v.x);
        ull vb = pk2(v.y, v.y);
#pragma unroll
        for (int g = 0; g < 8; ++g) {
            ulonglong2 ap = *(const ulonglong2*)&sa[s][g*4];
            fma2(acc[g*2+0][0], ap.x, va);
            fma2(acc[g*2+0][1], ap.x, vb);
            fma2(acc[g*2+1][0], ap.y, va);
            fma2(acc[g*2+1][1], ap.y, vb);
        }
    }

#pragma unroll
    for (int g = 0; g < 16; ++g) {
        float2 oA = upk(acc[g][0]);   // d0 column: (t even, t odd)
        float2 oB = upk(acc[g][1]);   // d0+1 column
        int t = t0 + g*2;
        *(float2*)(g_q + ((size_t)((b*64 + t  )*16 + h*2))*HW + d0) = make_float2(oA.x, oB.x);
        *(float2*)(g_q + ((size_t)((b*64 + t+1)*16 + h*2))*HW + d0) = make_float2(oA.y, oB.y);
    }
}

// ---------------- launch ----------------
extern "C" void kernel_launch(void* const* d_in, const int* in_sizes, int n_in,
                              void* d_out, int out_size)
{
    const float* x  = (const float*)d_in[0];
    const float* wq = (const float*)d_in[1];
    const float* bq = (const float*)d_in[2];
    const float* wk = (const float*)d_in[3];
    const float* bk = (const float*)d_in[4];
    const float* wv = (const float*)d_in[5];
    const float* bv = (const float*)d_in[6];
    const float* wo = (const float*)d_in[7];
    const float* bo = (const float*)d_in[8];
    float* out = (float*)d_out;

    const int smem3 = (24*160 + 16*216)*8 + 48*4;  // 58560 B
    const int smem1 = (8*160  + 16*216)*8 + 16*4;  // 37952 B
    cudaFuncSetAttribute(conv3x3_kernel<3>, cudaFuncAttributeMaxDynamicSharedMemorySize, smem3);
    cudaFuncSetAttribute(conv3x3_kernel<1>, cudaFuncAttributeMaxDynamicSharedMemorySize, smem1);

    dim3 cgrid(128, 128);   // 128 tiles (32x4) x 128 images
    conv3x3_kernel<3><<<cgrid, 128, smem3>>>(x, wq, bq, wk, bk, wv, bv, nullptr);
    qk_kernel<<<dim3(64, 16), 256>>>();
    softmax_kernel<<<dim3(64, 16), 64>>>();
    av_kernel<<<dim3(64, 2, 16), 256>>>();   // 64*512 = 32768 = D  (R6 bug: was 32)
    conv3x3_kernel<1><<<cgrid, 128, smem1>>>(nullptr, wo, bo, nullptr, nullptr,
                                             nullptr, nullptr, out);
}

// round 8
// speedup vs baseline: 1.2306x; 1.2306x over previous
#include <cuda_runtime.h>
#include <math.h>

// x: [B=2, T=64, C=16, H=128, W=128] f32; qkv conv 3x3 pad1 (16->16),
// nh=8, hc=2, D=32768; causal softmax T=64; out conv 3x3 (16->16).
#define HW 16384
typedef unsigned long long ull;

// ---------------- packed fp32x2 helpers (FFMA2 path, 2x fp32 tput) --------
__device__ __forceinline__ ull pk2(float lo, float hi) {
    ull r;
    asm("mov.b64 %0, {%1, %2};"
        : "=l"(r) : "r"(__float_as_uint(lo)), "r"(__float_as_uint(hi)));
    return r;
}
__device__ __forceinline__ void fma2(ull& d, ull a, ull b) {
    asm("fma.rn.f32x2 %0, %1, %2, %0;" : "+l"(d) : "l"(a), "l"(b));
}
__device__ __forceinline__ float2 upk(ull v) {
    unsigned lo, hi;
    asm("mov.b64 {%0, %1}, %2;" : "=r"(lo), "=r"(hi) : "l"(v));
    return make_float2(__uint_as_float(lo), __uint_as_float(hi));
}

// ---------------- scratch ----------------
__device__ float g_q[2*64*16*16384];   // q, later reused as attention output y
__device__ float g_k[2*64*16*16384];
__device__ float g_v[2*64*16*16384];
__device__ float g_part[64*16*64*64];  // QK^T partials per k-split
__device__ float g_att[16*64*64];      // softmax probs, [bh][s][t]

// ---------------- 3x3 conv, channel-pair FFMA2 (R5 proven variant) -------
// f32x2 lanes = two OUTPUT CHANNELS (2q, 2q+1). Block 128 thr = 4 warps
// (channel groups) x 32 pixel slots; tile 32w x 4h, thread = 4 pixels x
// PPG channel-pairs. Scalar pixel LDS + pk2 dup; 44KB smem -> 5 CTAs/SM.
template<int NCONV>
__global__ void __launch_bounds__(128) conv3x3_kernel(
    const float* __restrict__ xin,
    const float* __restrict__ w0, const float* __restrict__ b0,
    const float* __restrict__ w1, const float* __restrict__ b1,
    const float* __restrict__ w2, const float* __restrict__ b2,
    float* __restrict__ out_final)
{
    constexpr int NPAIR = NCONV * 8;     // channel pairs total
    constexpr int PPG   = NPAIR / 4;     // pairs per warp
    extern __shared__ ull dyn[];
    ull*   s_w2 = dyn;                          // NPAIR*16ic*10 packed (wA,wB)
    float* s_in = (float*)(dyn + NPAIR*160);    // 16c x 6row x 35 halo tile
    float* s_b  = s_in + 16*210;                // NCONV*16 biases

    const int tid = threadIdx.x;
    const int bt  = blockIdx.y;                 // image 0..127
    const int th0 = (blockIdx.x >> 2) * 4;      // tile origin h
    const int tw0 = (blockIdx.x & 3) * 32;      // tile origin w

    const float* x = (NCONV == 3) ? xin : g_q;  // final conv reads y (on g_q)

    // stage weights as channel-pair packs: [(pair*16+ic)*10 + j] = (w[2p], w[2p+1])
    {
        const float* wsrc[3] = {w0, w1, w2};
        for (int idx = tid; idx < NPAIR*144; idx += 128) {
            int pair = idx / 144;
            int r    = idx - pair*144;          // ic*9 + j
            int chA  = pair*2, chB = chA + 1;
            float a  = wsrc[chA >> 4][(chA & 15)*144 + r];
            float b  = wsrc[chB >> 4][(chB & 15)*144 + r];
            int ic   = r / 9;
            int j    = r - ic*9;
            s_w2[(pair*16 + ic)*10 + j] = pk2(a, b);
        }
        for (int idx = tid; idx < NCONV*16; idx += 128) {
            float bv;
            if (NCONV == 3) bv = (idx < 16) ? b0[idx] : (idx < 32 ? b1[idx-16] : b2[idx-32]);
            else            bv = b0[idx];
            s_b[idx] = bv;
        }
    }

    // stage input tile with halo: rows th0-1..th0+4, cols tw0-1..tw0+32
    for (int idx = tid; idx < 16*6*34; idx += 128) {
        int c   = idx / 204;
        int rem = idx - c*204;
        int yy  = rem / 34;
        int xx  = rem - yy*34;
        int gh  = th0 + yy - 1;
        int gw  = tw0 + xx - 1;
        float v = 0.f;
        if (gh >= 0 && gh < 128 && gw >= 0 && gw < 128)
            v = x[((size_t)bt*16 + c)*HW + gh*128 + gw];
        s_in[c*210 + yy*35 + xx] = v;
    }
    __syncthreads();

    const int cg  = tid >> 5;           // warp = channel group (PPG pairs)
    const int sl  = tid & 31;           // pixel slot
    const int py  = sl >> 3;            // tile row 0..3
    const int x0  = (sl & 7) * 4;       // tile col start

    ull acc[PPG][4];
#pragma unroll
    for (int c = 0; c < PPG; ++c) {
        int q = cg*PPG + c;
        ull b2 = pk2(s_b[2*q], s_b[2*q + 1]);
#pragma unroll
        for (int p = 0; p < 4; ++p) acc[c][p] = b2;
    }

    for (int ic = 0; ic < 16; ++ic) {
        const float* base = s_in + ic*210 + py*35 + x0;   // rows py..py+2
        ull pkk[3][6];
#pragma unroll
        for (int ky = 0; ky < 3; ++ky)
#pragma unroll
            for (int j = 0; j < 6; ++j) {
                float v = base[ky*35 + j];
                pkk[ky][j] = pk2(v, v);
            }
#pragma unroll
        for (int c = 0; c < PPG; ++c) {
            const ull* wp = s_w2 + ((cg*PPG + c)*16 + ic)*10;
            ulonglong2 wA = *(const ulonglong2*)wp;        // taps 0,1
            ulonglong2 wB = *(const ulonglong2*)(wp + 2);  // taps 2,3
            ulonglong2 wC = *(const ulonglong2*)(wp + 4);  // taps 4,5
            ulonglong2 wD = *(const ulonglong2*)(wp + 6);  // taps 6,7
            ull w8 = wp[8];
#pragma unroll
            for (int px = 0; px < 4; ++px) {
                ull a = acc[c][px];
                fma2(a, pkk[0][px+0], wA.x);
                fma2(a, pkk[0][px+1], wA.y);
                fma2(a, pkk[0][px+2], wB.x);
                fma2(a, pkk[1][px+0], wB.y);
                fma2(a, pkk[1][px+1], wC.x);
                fma2(a, pkk[1][px+2], wC.y);
                fma2(a, pkk[2][px+0], wD.x);
                fma2(a, pkk[2][px+1], wD.y);
                fma2(a, pkk[2][px+2], w8);
                acc[c][px] = a;
            }
        }
    }

    const int oh = th0 + py;
    const int ow = tw0 + x0;
#pragma unroll
    for (int c = 0; c < PPG; ++c) {
        int q    = cg*PPG + c;
        int chA  = 2*q, chB = chA + 1;
        float2 v0 = upk(acc[c][0]);
        float2 v1 = upk(acc[c][1]);
        float2 v2 = upk(acc[c][2]);
        float2 v3 = upk(acc[c][3]);
        float* outA;
        float* outB;
        if (NCONV == 3) {
            outA = (chA < 16) ? g_q : (chA < 32 ? g_k : g_v);
            outB = (chB < 16) ? g_q : (chB < 32 ? g_k : g_v);
        } else {
            outA = out_final; outB = out_final;
        }
        size_t offA = ((size_t)bt*16 + (chA & 15))*HW + oh*128 + ow;
        size_t offB = ((size_t)bt*16 + (chB & 15))*HW + oh*128 + ow;
        *(float4*)(outA + offA) = make_float4(v0.x, v1.x, v2.x, v3.x);
        *(float4*)(outB + offB) = make_float4(v0.y, v1.y, v2.y, v3.y);
    }
}

// ---------------- QK^T with K-split, FFMA2 inner ----------------
__global__ void __launch_bounds__(256) qk_kernel()
{
    __shared__ __align__(16) float Qs[64][68];
    __shared__ __align__(16) float Ks[64][68];
    const int bh = blockIdx.y;
    const int b  = bh >> 3, h = bh & 7;
    const int split = blockIdx.x;
    const int tid = threadIdx.x;
    const int ty = tid >> 4, tx = tid & 15;

    ull acc2[4][2];
#pragma unroll
    for (int i = 0; i < 4; ++i) { acc2[i][0] = 0ULL; acc2[i][1] = 0ULL; }

    for (int sub = 0; sub < 8; ++sub) {
        const int kc = split*512 + sub*64;
        __syncthreads();
        for (int i = tid; i < 1024; i += 256) {
            int t  = i >> 4;
            int kq = (i & 15) << 2;
            size_t base = ((size_t)((b*64 + t)*16 + h*2))*HW + kc + kq;
            float4 qa = *(const float4*)(g_q + base);
            float4 ka = *(const float4*)(g_k + base);
            Qs[kq+0][t] = qa.x; Qs[kq+1][t] = qa.y; Qs[kq+2][t] = qa.z; Qs[kq+3][t] = qa.w;
            Ks[kq+0][t] = ka.x; Ks[kq+1][t] = ka.y; Ks[kq+2][t] = ka.z; Ks[kq+3][t] = ka.w;
        }
        __syncthreads();
#pragma unroll 8
        for (int kk = 0; kk < 64; ++kk) {
            float4 a = *(const float4*)&Qs[kk][ty*4];
            ulonglong2 bp = *(const ulonglong2*)&Ks[kk][tx*4];
            ull a0 = pk2(a.x, a.x);
            ull a1 = pk2(a.y, a.y);
            ull a2 = pk2(a.z, a.z);
            ull a3 = pk2(a.w, a.w);
            fma2(acc2[0][0], a0, bp.x); fma2(acc2[0][1], a0, bp.y);
            fma2(acc2[1][0], a1, bp.x); fma2(acc2[1][1], a1, bp.y);
            fma2(acc2[2][0], a2, bp.x); fma2(acc2[2][1], a2, bp.y);
            fma2(acc2[3][0], a3, bp.x); fma2(acc2[3][1], a3, bp.y);
        }
    }

    float* dst = g_part + ((size_t)(split*16 + bh))*4096;
#pragma unroll
    for (int i = 0; i < 4; ++i) {
        float2 lo = upk(acc2[i][0]);
        float2 hi = upk(acc2[i][1]);
        *(float4*)(dst + (ty*4 + i)*64 + tx*4) = make_float4(lo.x, lo.y, hi.x, hi.y);
    }
}

// ---------------- split-reduce + causal softmax ----------------
__global__ void softmax_kernel()
{
    const int bh = blockIdx.y;
    const int t  = blockIdx.x;
    const int s  = threadIdx.x;

    float ssum = 0.f;
    for (int sp = 0; sp < 64; ++sp)
        ssum += g_part[((size_t)(sp*16 + bh)*64 + t)*64 + s];

    const float scale = rsqrtf(32768.0f);
    const bool valid = (s <= t);
    float logit = valid ? ssum * scale : -INFINITY;

    __shared__ float red[64];
    red[s] = logit;
    __syncthreads();
    for (int off = 32; off > 0; off >>= 1) {
        if (s < off) red[s] = fmaxf(red[s], red[s + off]);
        __syncthreads();
    }
    float mx = red[0];
    __syncthreads();
    float e = valid ? expf(logit - mx) : 0.f;
    red[s] = e;
    __syncthreads();
    for (int off = 32; off > 0; off >>= 1) {
        if (s < off) red[s] += red[s + off];
        __syncthreads();
    }
    float p = e / red[0];
    g_att[(bh*64 + s)*64 + t] = p;   // 0 for s > t
}

// ---------------- y = att @ V: 2 d-cols per thread, causal split ----------
// grid (64, 2, 16), block 256; thread = 2 consecutive d, 32 t (16 packed pairs).
__global__ void __launch_bounds__(256) av_kernel()
{
    __shared__ __align__(16) float sa[64][32];   // att[s][t0+tt]
    const int bh = blockIdx.z;
    const int b  = bh >> 3, h = bh & 7;
    const int thalf = blockIdx.y;
    const int t0 = thalf * 32;
    const int smax = thalf ? 64 : 32;   // causal: lower t-half only needs s<32
    const int d0 = blockIdx.x*512 + threadIdx.x*2;

    for (int i = threadIdx.x; i < smax*8; i += 256) {
        int s = i >> 3; int tg = i & 7;
        *(float4*)&sa[s][tg*4] = *(const float4*)(g_att + (bh*64 + s)*64 + t0 + tg*4);
    }
    __syncthreads();

    ull acc[16][2];
#pragma unroll
    for (int g = 0; g < 16; ++g) { acc[g][0] = 0ULL; acc[g][1] = 0ULL; }

    const size_t vbase = ((size_t)(b*64*16 + h*2))*HW + d0;
#pragma unroll 2
    for (int s = 0; s < smax; ++s) {
        float2 v = *(const float2*)(g_v + vbase + (size_t)s*16*HW);
        ull va = pk2(v.x, v.x);
        ull vb = pk2(v.y, v.y);
#pragma unroll
        for (int g = 0; g < 8; ++g) {
            ulonglong2 ap = *(const ulonglong2*)&sa[s][g*4];
            fma2(acc[g*2+0][0], ap.x, va);
            fma2(acc[g*2+0][1], ap.x, vb);
            fma2(acc[g*2+1][0], ap.y, va);
            fma2(acc[g*2+1][1], ap.y, vb);
        }
    }

#pragma unroll
    for (int g = 0; g < 16; ++g) {
        float2 oA = upk(acc[g][0]);   // d0 column: (t even, t odd)
        float2 oB = upk(acc[g][1]);   // d0+1 column
        int t = t0 + g*2;
        *(float2*)(g_q + ((size_t)((b*64 + t  )*16 + h*2))*HW + d0) = make_float2(oA.x, oB.x);
        *(float2*)(g_q + ((size_t)((b*64 + t+1)*16 + h*2))*HW + d0) = make_float2(oA.y, oB.y);
    }
}

// ---------------- launch ----------------
extern "C" void kernel_launch(void* const* d_in, const int* in_sizes, int n_in,
                              void* d_out, int out_size)
{
    const float* x  = (const float*)d_in[0];
    const float* wq = (const float*)d_in[1];
    const float* bq = (const float*)d_in[2];
    const float* wk = (const float*)d_in[3];
    const float* bk = (const float*)d_in[4];
    const float* wv = (const float*)d_in[5];
    const float* bv = (const float*)d_in[6];
    const float* wo = (const float*)d_in[7];
    const float* bo = (const float*)d_in[8];
    float* out = (float*)d_out;

    const int smem3 = 24*160*8 + 16*210*4 + 48*4;  // 44352 B  (5 CTAs/SM)
    const int smem1 = 8*160*8  + 16*210*4 + 16*4;  // 23744 B
    cudaFuncSetAttribute(conv3x3_kernel<3>, cudaFuncAttributeMaxDynamicSharedMemorySize, smem3);
    cudaFuncSetAttribute(conv3x3_kernel<1>, cudaFuncAttributeMaxDynamicSharedMemorySize, smem1);

    dim3 cgrid(128, 128);   // 128 tiles (32x4) x 128 images
    conv3x3_kernel<3><<<cgrid, 128, smem3>>>(x, wq, bq, wk, bk, wv, bv, nullptr);
    qk_kernel<<<dim3(64, 16), 256>>>();
    softmax_kernel<<<dim3(64, 16), 64>>>();
    av_kernel<<<dim3(64, 2, 16), 256>>>();   // 64*512 = 32768 = D
    conv3x3_kernel<1><<<cgrid, 128, smem1>>>(nullptr, wo, bo, nullptr, nullptr,
                                             nullptr, nullptr, out);
}

// round 9
// speedup vs baseline: 1.2332x; 1.0021x over previous
#include <cuda_runtime.h>
#include <cuda_bf16.h>
#include <math.h>

// x: [B=2, T=64, C=16, H=128, W=128] f32; qkv conv 3x3 pad1 (16->16),
// nh=8, hc=2, D=32768; causal softmax T=64; out conv 3x3 (16->16).
#define HW 16384
typedef unsigned long long ull;

// ---------------- packed fp32x2 helpers (FFMA2 path, 2x fp32 tput) --------
__device__ __forceinline__ ull pk2(float lo, float hi) {
    ull r;
    asm("mov.b64 %0, {%1, %2};"
        : "=l"(r) : "r"(__float_as_uint(lo)), "r"(__float_as_uint(hi)));
    return r;
}
__device__ __forceinline__ void fma2(ull& d, ull a, ull b) {
    asm("fma.rn.f32x2 %0, %1, %2, %0;" : "+l"(d) : "l"(a), "l"(b));
}
__device__ __forceinline__ float2 upk(ull v) {
    unsigned lo, hi;
    asm("mov.b64 {%0, %1}, %2;" : "=r"(lo), "=r"(hi) : "l"(v));
    return make_float2(__uint_as_float(lo), __uint_as_float(hi));
}

// ---------------- scratch ----------------
__device__ float         g_q[2*64*16*16384];   // y (attention output)
__device__ float         g_v[2*64*16*16384];   // v (fp32: precision-critical)
__device__ __nv_bfloat16 g_qh[2*64*16*16384];  // q in bf16 (only used in dot)
__device__ __nv_bfloat16 g_kh[2*64*16*16384];  // k in bf16
__device__ float g_part[64*16*64*64];          // QK^T partials per k-split
__device__ float g_att[16*64*64];              // softmax probs, [bh][s][t]

// ---------------- 3x3 conv, channel-pair FFMA2 (R5 proven variant) -------
// f32x2 lanes = two OUTPUT CHANNELS (2q, 2q+1). Block 128 thr = 4 warps
// (channel groups) x 32 pixel slots; tile 32w x 4h, thread = 4 pixels x
// PPG channel-pairs. q,k outputs stored bf16; v and final output fp32.
template<int NCONV>
__global__ void __launch_bounds__(128) conv3x3_kernel(
    const float* __restrict__ xin,
    const float* __restrict__ w0, const float* __restrict__ b0,
    const float* __restrict__ w1, const float* __restrict__ b1,
    const float* __restrict__ w2, const float* __restrict__ b2,
    float* __restrict__ out_final)
{
    constexpr int NPAIR = NCONV * 8;     // channel pairs total
    constexpr int PPG   = NPAIR / 4;     // pairs per warp
    extern __shared__ ull dyn[];
    ull*   s_w2 = dyn;                          // NPAIR*16ic*10 packed (wA,wB)
    float* s_in = (float*)(dyn + NPAIR*160);    // 16c x 6row x 35 halo tile
    float* s_b  = s_in + 16*210;                // NCONV*16 biases

    const int tid = threadIdx.x;
    const int bt  = blockIdx.y;                 // image 0..127
    const int th0 = (blockIdx.x >> 2) * 4;      // tile origin h
    const int tw0 = (blockIdx.x & 3) * 32;      // tile origin w

    const float* x = (NCONV == 3) ? xin : g_q;  // final conv reads y (on g_q)

    // stage weights as channel-pair packs: [(pair*16+ic)*10 + j] = (w[2p], w[2p+1])
    {
        const float* wsrc[3] = {w0, w1, w2};
        for (int idx = tid; idx < NPAIR*144; idx += 128) {
            int pair = idx / 144;
            int r    = idx - pair*144;          // ic*9 + j
            int chA  = pair*2, chB = chA + 1;
            float a  = wsrc[chA >> 4][(chA & 15)*144 + r];
            float b  = wsrc[chB >> 4][(chB & 15)*144 + r];
            int ic   = r / 9;
            int j    = r - ic*9;
            s_w2[(pair*16 + ic)*10 + j] = pk2(a, b);
        }
        for (int idx = tid; idx < NCONV*16; idx += 128) {
            float bv;
            if (NCONV == 3) bv = (idx < 16) ? b0[idx] : (idx < 32 ? b1[idx-16] : b2[idx-32]);
            else            bv = b0[idx];
            s_b[idx] = bv;
        }
    }

    // stage input tile with halo: rows th0-1..th0+4, cols tw0-1..tw0+32
    for (int idx = tid; idx < 16*6*34; idx += 128) {
        int c   = idx / 204;
        int rem = idx - c*204;
        int yy  = rem / 34;
        int xx  = rem - yy*34;
        int gh  = th0 + yy - 1;
        int gw  = tw0 + xx - 1;
        float v = 0.f;
        if (gh >= 0 && gh < 128 && gw >= 0 && gw < 128)
            v = x[((size_t)bt*16 + c)*HW + gh*128 + gw];
        s_in[c*210 + yy*35 + xx] = v;
    }
    __syncthreads();

    const int cg  = tid >> 5;           // warp = channel group (PPG pairs)
    const int sl  = tid & 31;           // pixel slot
    const int py  = sl >> 3;            // tile row 0..3
    const int x0  = (sl & 7) * 4;       // tile col start

    ull acc[PPG][4];
#pragma unroll
    for (int c = 0; c < PPG; ++c) {
        int q = cg*PPG + c;
        ull b2 = pk2(s_b[2*q], s_b[2*q + 1]);
#pragma unroll
        for (int p = 0; p < 4; ++p) acc[c][p] = b2;
    }

    for (int ic = 0; ic < 16; ++ic) {
        const float* base = s_in + ic*210 + py*35 + x0;   // rows py..py+2
        ull pkk[3][6];
#pragma unroll
        for (int ky = 0; ky < 3; ++ky)
#pragma unroll
            for (int j = 0; j < 6; ++j) {
                float v = base[ky*35 + j];
                pkk[ky][j] = pk2(v, v);
            }
#pragma unroll
        for (int c = 0; c < PPG; ++c) {
            const ull* wp = s_w2 + ((cg*PPG + c)*16 + ic)*10;
            ulonglong2 wA = *(const ulonglong2*)wp;        // taps 0,1
            ulonglong2 wB = *(const ulonglong2*)(wp + 2);  // taps 2,3
            ulonglong2 wC = *(const ulonglong2*)(wp + 4);  // taps 4,5
            ulonglong2 wD = *(const ulonglong2*)(wp + 6);  // taps 6,7
            ull w8 = wp[8];
#pragma unroll
            for (int px = 0; px < 4; ++px) {
                ull a = acc[c][px];
                fma2(a, pkk[0][px+0], wA.x);
                fma2(a, pkk[0][px+1], wA.y);
                fma2(a, pkk[0][px+2], wB.x);
                fma2(a, pkk[1][px+0], wB.y);
                fma2(a, pkk[1][px+1], wC.x);
                fma2(a, pkk[1][px+2], wC.y);
                fma2(a, pkk[2][px+0], wD.x);
                fma2(a, pkk[2][px+1], wD.y);
                fma2(a, pkk[2][px+2], w8);
                acc[c][px] = a;
            }
        }
    }

    const int oh = th0 + py;
    const int ow = tw0 + x0;
#pragma unroll
    for (int c = 0; c < PPG; ++c) {
        int q2   = cg*PPG + c;
        int chA  = 2*q2;                 // even; pair never straddles convs
        int conv = chA >> 4;
        int ocA  = chA & 15;
        size_t offA = ((size_t)bt*16 + ocA)*HW + oh*128 + ow;
        size_t offB = offA + HW;         // channel ocA+1
        float2 v0 = upk(acc[c][0]);
        float2 v1 = upk(acc[c][1]);
        float2 v2 = upk(acc[c][2]);
        float2 v3 = upk(acc[c][3]);
        if (NCONV == 1) {
            *(float4*)(out_final + offA) = make_float4(v0.x, v1.x, v2.x, v3.x);
            *(float4*)(out_final + offB) = make_float4(v0.y, v1.y, v2.y, v3.y);
        } else if (conv == 2) {          // v: fp32
            *(float4*)(g_v + offA) = make_float4(v0.x, v1.x, v2.x, v3.x);
            *(float4*)(g_v + offB) = make_float4(v0.y, v1.y, v2.y, v3.y);
        } else {                          // q or k: bf16
            __nv_bfloat16* dst = (conv == 0) ? g_qh : g_kh;
            __nv_bfloat162 a0 = __floats2bfloat162_rn(v0.x, v1.x);
            __nv_bfloat162 a1 = __floats2bfloat162_rn(v2.x, v3.x);
            __nv_bfloat162 b0p = __floats2bfloat162_rn(v0.y, v1.y);
            __nv_bfloat162 b1p = __floats2bfloat162_rn(v2.y, v3.y);
            uint2 uA, uB;
            uA.x = *(unsigned*)&a0;  uA.y = *(unsigned*)&a1;
            uB.x = *(unsigned*)&b0p; uB.y = *(unsigned*)&b1p;
            *(uint2*)(dst + offA) = uA;
            *(uint2*)(dst + offB) = uB;
        }
    }
}

// ---------------- QK^T with K-split, FFMA2 inner (bf16 q/k input) ---------
__global__ void __launch_bounds__(256) qk_kernel()
{
    __shared__ __align__(16) float Qs[64][68];
    __shared__ __align__(16) float Ks[64][68];
    const int bh = blockIdx.y;
    const int b  = bh >> 3, h = bh & 7;
    const int split = blockIdx.x;
    const int tid = threadIdx.x;
    const int ty = tid >> 4, tx = tid & 15;

    ull acc2[4][2];
#pragma unroll
    for (int i = 0; i < 4; ++i) { acc2[i][0] = 0ULL; acc2[i][1] = 0ULL; }

    for (int sub = 0; sub < 8; ++sub) {
        const int kc = split*512 + sub*64;
        __syncthreads();
        for (int i = tid; i < 1024; i += 256) {
            int t  = i >> 4;
            int kq = (i & 15) << 2;
            size_t base = ((size_t)((b*64 + t)*16 + h*2))*HW + kc + kq;
            uint2 qr = *(const uint2*)(g_qh + base);   // 4 bf16
            uint2 kr = *(const uint2*)(g_kh + base);
            float2 q01 = __bfloat1622float2(*(const __nv_bfloat162*)&qr.x);
            float2 q23 = __bfloat1622float2(*(const __nv_bfloat162*)&qr.y);
            float2 k01 = __bfloat1622float2(*(const __nv_bfloat162*)&kr.x);
            float2 k23 = __bfloat1622float2(*(const __nv_bfloat162*)&kr.y);
            Qs[kq+0][t] = q01.x; Qs[kq+1][t] = q01.y; Qs[kq+2][t] = q23.x; Qs[kq+3][t] = q23.y;
            Ks[kq+0][t] = k01.x; Ks[kq+1][t] = k01.y; Ks[kq+2][t] = k23.x; Ks[kq+3][t] = k23.y;
        }
        __syncthreads();
#pragma unroll 8
        for (int kk = 0; kk < 64; ++kk) {
            float4 a = *(const float4*)&Qs[kk][ty*4];
            ulonglong2 bp = *(const ulonglong2*)&Ks[kk][tx*4];
            ull a0 = pk2(a.x, a.x);
            ull a1 = pk2(a.y, a.y);
            ull a2 = pk2(a.z, a.z);
            ull a3 = pk2(a.w, a.w);
            fma2(acc2[0][0], a0, bp.x); fma2(acc2[0][1], a0, bp.y);
            fma2(acc2[1][0], a1, bp.x); fma2(acc2[1][1], a1, bp.y);
            fma2(acc2[2][0], a2, bp.x); fma2(acc2[2][1], a2, bp.y);
            fma2(acc2[3][0], a3, bp.x); fma2(acc2[3][1], a3, bp.y);
        }
    }

    float* dst = g_part + ((size_t)(split*16 + bh))*4096;
#pragma unroll
    for (int i = 0; i < 4; ++i) {
        float2 lo = upk(acc2[i][0]);
        float2 hi = upk(acc2[i][1]);
        *(float4*)(dst + (ty*4 + i)*64 + tx*4) = make_float4(lo.x, lo.y, hi.x, hi.y);
    }
}

// ---------------- split-reduce + causal softmax ----------------
__global__ void softmax_kernel()
{
    const int bh = blockIdx.y;
    const int t  = blockIdx.x;
    const int s  = threadIdx.x;

    float ssum = 0.f;
    for (int sp = 0; sp < 64; ++sp)
        ssum += g_part[((size_t)(sp*16 + bh)*64 + t)*64 + s];

    const float scale = rsqrtf(32768.0f);
    const bool valid = (s <= t);
    float logit = valid ? ssum * scale : -INFINITY;

    __shared__ float red[64];
    red[s] = logit;
    __syncthreads();
    for (int off = 32; off > 0; off >>= 1) {
        if (s < off) red[s] = fmaxf(red[s], red[s + off]);
        __syncthreads();
    }
    float mx = red[0];
    __syncthreads();
    float e = valid ? expf(logit - mx) : 0.f;
    red[s] = e;
    __syncthreads();
    for (int off = 32; off > 0; off >>= 1) {
        if (s < off) red[s] += red[s + off];
        __syncthreads();
    }
    float p = e / red[0];
    g_att[(bh*64 + s)*64 + t] = p;   // 0 for s > t
}

// ---------------- y = att @ V: 2 d-cols per thread, causal split ----------
// grid (64, 2, 16), block 256; thread = 2 consecutive d, 32 t (16 packed pairs).
__global__ void __launch_bounds__(256) av_kernel()
{
    __shared__ __align__(16) float sa[64][32];   // att[s][t0+tt]
    const int bh = blockIdx.z;
    const int b  = bh >> 3, h = bh & 7;
    const int thalf = blockIdx.y;
    const int t0 = thalf * 32;
    const int smax = thalf ? 64 : 32;   // causal: lower t-half only needs s<32
    const int d0 = blockIdx.x*512 + threadIdx.x*2;

    for (int i = threadIdx.x; i < smax*8; i += 256) {
        int s = i >> 3; int tg = i & 7;
        *(float4*)&sa[s][tg*4] = *(const float4*)(g_att + (bh*64 + s)*64 + t0 + tg*4);
    }
    __syncthreads();

    ull acc[16][2];
#pragma unroll
    for (int g = 0; g < 16; ++g) { acc[g][0] = 0ULL; acc[g][1] = 0ULL; }

    const size_t vbase = ((size_t)(b*64*16 + h*2))*HW + d0;
#pragma unroll 2
    for (int s = 0; s < smax; ++s) {
        float2 v = *(const float2*)(g_v + vbase + (size_t)s*16*HW);
        ull va = pk2(v.x, v.x);
        ull vb = pk2(v.y, v.y);
#pragma unroll
        for (int g = 0; g < 8; ++g) {
            ulonglong2 ap = *(const ulonglong2*)&sa[s][g*4];
            fma2(acc[g*2+0][0], ap.x, va);
            fma2(acc[g*2+0][1], ap.x, vb);
            fma2(acc[g*2+1][0], ap.y, va);
            fma2(acc[g*2+1][1], ap.y, vb);
        }
    }

#pragma unroll
    for (int g = 0; g < 16; ++g) {
        float2 oA = upk(acc[g][0]);   // d0 column: (t even, t odd)
        float2 oB = upk(acc[g][1]);   // d0+1 column
        int t = t0 + g*2;
        *(float2*)(g_q + ((size_t)((b*64 + t  )*16 + h*2))*HW + d0) = make_float2(oA.x, oB.x);
        *(float2*)(g_q + ((size_t)((b*64 + t+1)*16 + h*2))*HW + d0) = make_float2(oA.y, oB.y);
    }
}

// ---------------- launch ----------------
extern "C" void kernel_launch(void* const* d_in, const int* in_sizes, int n_in,
                              void* d_out, int out_size)
{
    const float* x  = (const float*)d_in[0];
    const float* wq = (const float*)d_in[1];
    const float* bq = (const float*)d_in[2];
    const float* wk = (const float*)d_in[3];
    const float* bk = (const float*)d_in[4];
    const float* wv = (const float*)d_in[5];
    const float* bv = (const float*)d_in[6];
    const float* wo = (const float*)d_in[7];
    const float* bo = (const float*)d_in[8];
    float* out = (float*)d_out;

    const int smem3 = 24*160*8 + 16*210*4 + 48*4;  // 44352 B
    const int smem1 = 8*160*8  + 16*210*4 + 16*4;  // 23744 B
    cudaFuncSetAttribute(conv3x3_kernel<3>, cudaFuncAttributeMaxDynamicSharedMemorySize, smem3);
    cudaFuncSetAttribute(conv3x3_kernel<1>, cudaFuncAttributeMaxDynamicSharedMemorySize, smem1);

    dim3 cgrid(128, 128);   // 128 tiles (32x4) x 128 images
    conv3x3_kernel<3><<<cgrid, 128, smem3>>>(x, wq, bq, wk, bk, wv, bv, nullptr);
    qk_kernel<<<dim3(64, 16), 256>>>();
    softmax_kernel<<<dim3(64, 16), 64>>>();
    av_kernel<<<dim3(64, 2, 16), 256>>>();
    conv3x3_kernel<1><<<cgrid, 128, smem1>>>(nullptr, wo, bo, nullptr, nullptr,
                                             nullptr, nullptr, out);
}

// round 10
// speedup vs baseline: 1.2664x; 1.0269x over previous
#include <cuda_runtime.h>
#include <cuda_bf16.h>
#include <math.h>

// x: [B=2, T=64, C=16, H=128, W=128] f32; qkv conv 3x3 pad1 (16->16),
// nh=8, hc=2, D=32768; causal softmax T=64; out conv 3x3 (16->16).
#define HW 16384
typedef unsigned long long ull;

// ---------------- packed fp32x2 helpers (FFMA2 path, 2x fp32 tput) --------
__device__ __forceinline__ ull pk2(float lo, float hi) {
    ull r;
    asm("mov.b64 %0, {%1, %2};"
        : "=l"(r) : "r"(__float_as_uint(lo)), "r"(__float_as_uint(hi)));
    return r;
}
__device__ __forceinline__ void fma2(ull& d, ull a, ull b) {
    asm("fma.rn.f32x2 %0, %1, %2, %0;" : "+l"(d) : "l"(a), "l"(b));
}
__device__ __forceinline__ float2 upk(ull v) {
    unsigned lo, hi;
    asm("mov.b64 {%0, %1}, %2;" : "=r"(lo), "=r"(hi) : "l"(v));
    return make_float2(__uint_as_float(lo), __uint_as_float(hi));
}

// ---------------- scratch ----------------
__device__ float         g_q[2*64*16*16384];   // y (attention output)
__device__ float         g_v[2*64*16*16384];   // v (fp32: precision-critical)
__device__ __nv_bfloat16 g_qh[2*64*16*16384];  // q in bf16 (only used in dot)
__device__ __nv_bfloat16 g_kh[2*64*16*16384];  // k in bf16
__device__ float g_part[64*16*64*64];          // QK^T partials per k-split
__device__ float g_att[16*64*64];              // softmax probs, [bh][s][t]

// ---------------- 3x3 conv, channel-pair FFMA2 (proven R8/R9 variant) ----
template<int NCONV>
__global__ void __launch_bounds__(128) conv3x3_kernel(
    const float* __restrict__ xin,
    const float* __restrict__ w0, const float* __restrict__ b0,
    const float* __restrict__ w1, const float* __restrict__ b1,
    const float* __restrict__ w2, const float* __restrict__ b2,
    float* __restrict__ out_final)
{
    constexpr int NPAIR = NCONV * 8;     // channel pairs total
    constexpr int PPG   = NPAIR / 4;     // pairs per warp
    extern __shared__ ull dyn[];
    ull*   s_w2 = dyn;                          // NPAIR*16ic*10 packed (wA,wB)
    float* s_in = (float*)(dyn + NPAIR*160);    // 16c x 6row x 35 halo tile
    float* s_b  = s_in + 16*210;                // NCONV*16 biases

    const int tid = threadIdx.x;
    const int bt  = blockIdx.y;                 // image 0..127
    const int th0 = (blockIdx.x >> 2) * 4;      // tile origin h
    const int tw0 = (blockIdx.x & 3) * 32;      // tile origin w

    const float* x = (NCONV == 3) ? xin : g_q;  // final conv reads y (on g_q)

    {
        const float* wsrc[3] = {w0, w1, w2};
        for (int idx = tid; idx < NPAIR*144; idx += 128) {
            int pair = idx / 144;
            int r    = idx - pair*144;          // ic*9 + j
            int chA  = pair*2, chB = chA + 1;
            float a  = wsrc[chA >> 4][(chA & 15)*144 + r];
            float b  = wsrc[chB >> 4][(chB & 15)*144 + r];
            int ic   = r / 9;
            int j    = r - ic*9;
            s_w2[(pair*16 + ic)*10 + j] = pk2(a, b);
        }
        for (int idx = tid; idx < NCONV*16; idx += 128) {
            float bv;
            if (NCONV == 3) bv = (idx < 16) ? b0[idx] : (idx < 32 ? b1[idx-16] : b2[idx-32]);
            else            bv = b0[idx];
            s_b[idx] = bv;
        }
    }

    for (int idx = tid; idx < 16*6*34; idx += 128) {
        int c   = idx / 204;
        int rem = idx - c*204;
        int yy  = rem / 34;
        int xx  = rem - yy*34;
        int gh  = th0 + yy - 1;
        int gw  = tw0 + xx - 1;
        float v = 0.f;
        if (gh >= 0 && gh < 128 && gw >= 0 && gw < 128)
            v = x[((size_t)bt*16 + c)*HW + gh*128 + gw];
        s_in[c*210 + yy*35 + xx] = v;
    }
    __syncthreads();

    const int cg  = tid >> 5;
    const int sl  = tid & 31;
    const int py  = sl >> 3;
    const int x0  = (sl & 7) * 4;

    ull acc[PPG][4];
#pragma unroll
    for (int c = 0; c < PPG; ++c) {
        int q = cg*PPG + c;
        ull b2 = pk2(s_b[2*q], s_b[2*q + 1]);
#pragma unroll
        for (int p = 0; p < 4; ++p) acc[c][p] = b2;
    }

    for (int ic = 0; ic < 16; ++ic) {
        const float* base = s_in + ic*210 + py*35 + x0;
        ull pkk[3][6];
#pragma unroll
        for (int ky = 0; ky < 3; ++ky)
#pragma unroll
            for (int j = 0; j < 6; ++j) {
                float v = base[ky*35 + j];
                pkk[ky][j] = pk2(v, v);
            }
#pragma unroll
        for (int c = 0; c < PPG; ++c) {
            const ull* wp = s_w2 + ((cg*PPG + c)*16 + ic)*10;
            ulonglong2 wA = *(const ulonglong2*)wp;
            ulonglong2 wB = *(const ulonglong2*)(wp + 2);
            ulonglong2 wC = *(const ulonglong2*)(wp + 4);
            ulonglong2 wD = *(const ulonglong2*)(wp + 6);
            ull w8 = wp[8];
#pragma unroll
            for (int px = 0; px < 4; ++px) {
                ull a = acc[c][px];
                fma2(a, pkk[0][px+0], wA.x);
                fma2(a, pkk[0][px+1], wA.y);
                fma2(a, pkk[0][px+2], wB.x);
                fma2(a, pkk[1][px+0], wB.y);
                fma2(a, pkk[1][px+1], wC.x);
                fma2(a, pkk[1][px+2], wC.y);
                fma2(a, pkk[2][px+0], wD.x);
                fma2(a, pkk[2][px+1], wD.y);
                fma2(a, pkk[2][px+2], w8);
                acc[c][px] = a;
            }
        }
    }

    const int oh = th0 + py;
    const int ow = tw0 + x0;
#pragma unroll
    for (int c = 0; c < PPG; ++c) {
        int q2   = cg*PPG + c;
        int chA  = 2*q2;                 // even; pair never straddles convs
        int conv = chA >> 4;
        int ocA  = chA & 15;
        size_t offA = ((size_t)bt*16 + ocA)*HW + oh*128 + ow;
        size_t offB = offA + HW;
        float2 v0 = upk(acc[c][0]);
        float2 v1 = upk(acc[c][1]);
        float2 v2 = upk(acc[c][2]);
        float2 v3 = upk(acc[c][3]);
        if (NCONV == 1) {
            *(float4*)(out_final + offA) = make_float4(v0.x, v1.x, v2.x, v3.x);
            *(float4*)(out_final + offB) = make_float4(v0.y, v1.y, v2.y, v3.y);
        } else if (conv == 2) {          // v: fp32
            *(float4*)(g_v + offA) = make_float4(v0.x, v1.x, v2.x, v3.x);
            *(float4*)(g_v + offB) = make_float4(v0.y, v1.y, v2.y, v3.y);
        } else {                          // q or k: bf16
            __nv_bfloat16* dst = (conv == 0) ? g_qh : g_kh;
            __nv_bfloat162 a0 = __floats2bfloat162_rn(v0.x, v1.x);
            __nv_bfloat162 a1 = __floats2bfloat162_rn(v2.x, v3.x);
            __nv_bfloat162 b0p = __floats2bfloat162_rn(v0.y, v1.y);
            __nv_bfloat162 b1p = __floats2bfloat162_rn(v2.y, v3.y);
            uint2 uA, uB;
            uA.x = *(unsigned*)&a0;  uA.y = *(unsigned*)&a1;
            uB.x = *(unsigned*)&b0p; uB.y = *(unsigned*)&b1p;
            *(uint2*)(dst + offA) = uA;
            *(uint2*)(dst + offB) = uB;
        }
    }
}

// ---------------- QK^T: 2-stage pipelined staging, FFMA2 inner -----------
// Dynamic smem: 2 stages x (Qs[64][68] + Ks[64][68]) = 69632 B.
// Prefetch sub+1's q/k (bf16) into regs while computing sub from smem.
__global__ void __launch_bounds__(256, 3) qk_kernel()
{
    extern __shared__ float sm[];       // stage stride 8704 floats
    const int bh = blockIdx.y;
    const int b  = bh >> 3, h = bh & 7;
    const int split = blockIdx.x;
    const int tid = threadIdx.x;
    const int ty = tid >> 4, tx = tid & 15;

    // this thread's 4 staging slots: i = tid + j*256 -> (t, kq)
    int st_t[4], st_kq[4];
#pragma unroll
    for (int j = 0; j < 4; ++j) {
        int i = tid + j*256;
        st_t[j]  = i >> 4;
        st_kq[j] = (i & 15) << 2;
    }

    uint2 qr[4], kr[4];
    // prefetch sub 0
    {
        const int kc = split*512;
#pragma unroll
        for (int j = 0; j < 4; ++j) {
            size_t base = ((size_t)((b*64 + st_t[j])*16 + h*2))*HW + kc + st_kq[j];
            qr[j] = *(const uint2*)(g_qh + base);
            kr[j] = *(const uint2*)(g_kh + base);
        }
    }

    ull acc2[4][2];
#pragma unroll
    for (int i = 0; i < 4; ++i) { acc2[i][0] = 0ULL; acc2[i][1] = 0ULL; }

    for (int sub = 0; sub < 8; ++sub) {
        float* Qs = sm + (sub & 1)*8704;
        float* Ks = Qs + 4352;
        __syncthreads();   // buf[sub&1] free (its last readers were sub-2)
        // store prefetched regs (bf16 -> fp32) into smem
#pragma unroll
        for (int j = 0; j < 4; ++j) {
            float2 q01 = __bfloat1622float2(*(const __nv_bfloat162*)&qr[j].x);
            float2 q23 = __bfloat1622float2(*(const __nv_bfloat162*)&qr[j].y);
            float2 k01 = __bfloat1622float2(*(const __nv_bfloat162*)&kr[j].x);
            float2 k23 = __bfloat1622float2(*(const __nv_bfloat162*)&kr[j].y);
            int t = st_t[j], kq = st_kq[j];
            Qs[(kq+0)*68 + t] = q01.x; Qs[(kq+1)*68 + t] = q01.y;
            Qs[(kq+2)*68 + t] = q23.x; Qs[(kq+3)*68 + t] = q23.y;
            Ks[(kq+0)*68 + t] = k01.x; Ks[(kq+1)*68 + t] = k01.y;
            Ks[(kq+2)*68 + t] = k23.x; Ks[(kq+3)*68 + t] = k23.y;
        }
        // prefetch next sub while this one computes
        if (sub < 7) {
            const int kc = split*512 + (sub+1)*64;
#pragma unroll
            for (int j = 0; j < 4; ++j) {
                size_t base = ((size_t)((b*64 + st_t[j])*16 + h*2))*HW + kc + st_kq[j];
                qr[j] = *(const uint2*)(g_qh + base);
                kr[j] = *(const uint2*)(g_kh + base);
            }
        }
        __syncthreads();   // staging visible
#pragma unroll 8
        for (int kk = 0; kk < 64; ++kk) {
            float4 a = *(const float4*)(Qs + kk*68 + ty*4);
            ulonglong2 bp = *(const ulonglong2*)(Ks + kk*68 + tx*4);
            ull a0 = pk2(a.x, a.x);
            ull a1 = pk2(a.y, a.y);
            ull a2 = pk2(a.z, a.z);
            ull a3 = pk2(a.w, a.w);
            fma2(acc2[0][0], a0, bp.x); fma2(acc2[0][1], a0, bp.y);
            fma2(acc2[1][0], a1, bp.x); fma2(acc2[1][1], a1, bp.y);
            fma2(acc2[2][0], a2, bp.x); fma2(acc2[2][1], a2, bp.y);
            fma2(acc2[3][0], a3, bp.x); fma2(acc2[3][1], a3, bp.y);
        }
    }

    float* dst = g_part + ((size_t)(split*16 + bh))*4096;
#pragma unroll
    for (int i = 0; i < 4; ++i) {
        float2 lo = upk(acc2[i][0]);
        float2 hi = upk(acc2[i][1]);
        *(float4*)(dst + (ty*4 + i)*64 + tx*4) = make_float4(lo.x, lo.y, hi.x, hi.y);
    }
}

// ---------------- split-reduce + causal softmax ----------------
__global__ void softmax_kernel()
{
    const int bh = blockIdx.y;
    const int t  = blockIdx.x;
    const int s  = threadIdx.x;

    float ssum = 0.f;
    for (int sp = 0; sp < 64; ++sp)
        ssum += g_part[((size_t)(sp*16 + bh)*64 + t)*64 + s];

    const float scale = rsqrtf(32768.0f);
    const bool valid = (s <= t);
    float logit = valid ? ssum * scale : -INFINITY;

    __shared__ float red[64];
    red[s] = logit;
    __syncthreads();
    for (int off = 32; off > 0; off >>= 1) {
        if (s < off) red[s] = fmaxf(red[s], red[s + off]);
        __syncthreads();
    }
    float mx = red[0];
    __syncthreads();
    float e = valid ? expf(logit - mx) : 0.f;
    red[s] = e;
    __syncthreads();
    for (int off = 32; off > 0; off >>= 1) {
        if (s < off) red[s] += red[s + off];
        __syncthreads();
    }
    float p = e / red[0];
    g_att[(bh*64 + s)*64 + t] = p;   // 0 for s > t
}

// ---------------- y = att @ V: 2 d/thread, MLP=4 v batching ---------------
// grid (64, 2, 16), block 256; thread = 2 consecutive d, 32 t (16 packed pairs).
__global__ void __launch_bounds__(256, 2) av_kernel()
{
    __shared__ __align__(16) float sa[64][32];   // att[s][t0+tt]
    const int bh = blockIdx.z;
    const int b  = bh >> 3, h = bh & 7;
    const int thalf = blockIdx.y;
    const int t0 = thalf * 32;
    const int smax = thalf ? 64 : 32;   // causal: lower t-half only needs s<32
    const int d0 = blockIdx.x*512 + threadIdx.x*2;

    for (int i = threadIdx.x; i < smax*8; i += 256) {
        int s = i >> 3; int tg = i & 7;
        *(float4*)&sa[s][tg*4] = *(const float4*)(g_att + (bh*64 + s)*64 + t0 + tg*4);
    }
    __syncthreads();

    ull acc[16][2];
#pragma unroll
    for (int g = 0; g < 16; ++g) { acc[g][0] = 0ULL; acc[g][1] = 0ULL; }

    const size_t vbase = ((size_t)(b*64*16 + h*2))*HW + d0;
    for (int s0 = 0; s0 < smax; s0 += 4) {
        float2 vv[4];
#pragma unroll
        for (int j = 0; j < 4; ++j)                 // 4 outstanding LDG.64
            vv[j] = *(const float2*)(g_v + vbase + (size_t)(s0 + j)*16*HW);
#pragma unroll
        for (int j = 0; j < 4; ++j) {
            ull va = pk2(vv[j].x, vv[j].x);
            ull vb = pk2(vv[j].y, vv[j].y);
            const int s = s0 + j;
#pragma unroll
            for (int g = 0; g < 8; ++g) {
                ulonglong2 ap = *(const ulonglong2*)&sa[s][g*4];
                fma2(acc[g*2+0][0], ap.x, va);
                fma2(acc[g*2+0][1], ap.x, vb);
                fma2(acc[g*2+1][0], ap.y, va);
                fma2(acc[g*2+1][1], ap.y, vb);
            }
        }
    }

#pragma unroll
    for (int g = 0; g < 16; ++g) {
        float2 oA = upk(acc[g][0]);   // d0 column: (t even, t odd)
        float2 oB = upk(acc[g][1]);   // d0+1 column
        int t = t0 + g*2;
        *(float2*)(g_q + ((size_t)((b*64 + t  )*16 + h*2))*HW + d0) = make_float2(oA.x, oB.x);
        *(float2*)(g_q + ((size_t)((b*64 + t+1)*16 + h*2))*HW + d0) = make_float2(oA.y, oB.y);
    }
}

// ---------------- launch ----------------
extern "C" void kernel_launch(void* const* d_in, const int* in_sizes, int n_in,
                              void* d_out, int out_size)
{
    const float* x  = (const float*)d_in[0];
    const float* wq = (const float*)d_in[1];
    const float* bq = (const float*)d_in[2];
    const float* wk = (const float*)d_in[3];
    const float* bk = (const float*)d_in[4];
    const float* wv = (const float*)d_in[5];
    const float* bv = (const float*)d_in[6];
    const float* wo = (const float*)d_in[7];
    const float* bo = (const float*)d_in[8];
    float* out = (float*)d_out;

    const int smem3 = 24*160*8 + 16*210*4 + 48*4;  // 44352 B
    const int smem1 = 8*160*8  + 16*210*4 + 16*4;  // 23744 B
    const int smemQK = 2 * 2 * 4352 * 4;           // 69632 B
    cudaFuncSetAttribute(conv3x3_kernel<3>, cudaFuncAttributeMaxDynamicSharedMemorySize, smem3);
    cudaFuncSetAttribute(conv3x3_kernel<1>, cudaFuncAttributeMaxDynamicSharedMemorySize, smem1);
    cudaFuncSetAttribute(qk_kernel, cudaFuncAttributeMaxDynamicSharedMemorySize, smemQK);

    dim3 cgrid(128, 128);   // 128 tiles (32x4) x 128 images
    conv3x3_kernel<3><<<cgrid, 128, smem3>>>(x, wq, bq, wk, bk, wv, bv, nullptr);
    qk_kernel<<<dim3(64, 16), 256, smemQK>>>();
    softmax_kernel<<<dim3(64, 16), 64>>>();
    av_kernel<<<dim3(64, 2, 16), 256>>>();
    conv3x3_kernel<1><<<cgrid, 128, smem1>>>(nullptr, wo, bo, nullptr, nullptr,
                                             nullptr, nullptr, out);
}

// round 11
// speedup vs baseline: 1.4018x; 1.1069x over previous
#include <cuda_runtime.h>
#include <cuda_bf16.h>
#include <math.h>

// x: [B=2, T=64, C=16, H=128, W=128] f32; qkv conv 3x3 pad1 (16->16),
// nh=8, hc=2, D=32768; causal softmax T=64; out conv 3x3 (16->16).
#define HW 16384
typedef unsigned long long ull;

// ---------------- packed fp32x2 helpers (FFMA2 path, 2x fp32 tput) --------
__device__ __forceinline__ ull pk2(float lo, float hi) {
    ull r;
    asm("mov.b64 %0, {%1, %2};"
        : "=l"(r) : "r"(__float_as_uint(lo)), "r"(__float_as_uint(hi)));
    return r;
}
__device__ __forceinline__ void fma2(ull& d, ull a, ull b) {
    asm("fma.rn.f32x2 %0, %1, %2, %0;" : "+l"(d) : "l"(a), "l"(b));
}
__device__ __forceinline__ float2 upk(ull v) {
    unsigned lo, hi;
    asm("mov.b64 {%0, %1}, %2;" : "=r"(lo), "=r"(hi) : "l"(v));
    return make_float2(__uint_as_float(lo), __uint_as_float(hi));
}

// ---------------- scratch ----------------
__device__ float         g_q[2*64*16*16384];   // y (attention output)
__device__ float         g_v[2*64*16*16384];   // v (fp32: precision-critical)
__device__ __nv_bfloat16 g_qh[2*64*16*16384];  // q in bf16 (only used in dot)
__device__ __nv_bfloat16 g_kh[2*64*16*16384];  // k in bf16
__device__ float g_part[64*16*64*64];          // QK^T partials per k-split
__device__ float g_att[16*64*64];              // softmax probs, [bh][s][t]

// ---------------- 3x3 conv, channel-pair FFMA2, pipelined staging ---------
// f32x2 lanes = two OUTPUT CHANNELS. Input halo tile staged in TWO channel
// groups (ic 0..7, 8..15); group B's LDG latency hides under group A's
// compute. Block 128 thr = 4 warps x 32 px slots; tile 32w x 4h.
template<int NCONV>
__global__ void __launch_bounds__(128) conv3x3_kernel(
    const float* __restrict__ xin,
    const float* __restrict__ w0, const float* __restrict__ b0,
    const float* __restrict__ w1, const float* __restrict__ b1,
    const float* __restrict__ w2, const float* __restrict__ b2,
    float* __restrict__ out_final)
{
    constexpr int NPAIR = NCONV * 8;     // channel pairs total
    constexpr int PPG   = NPAIR / 4;     // pairs per warp
    extern __shared__ ull dyn[];
    ull*   s_w2 = dyn;                          // NPAIR*16ic*10 packed (wA,wB)
    float* s_in = (float*)(dyn + NPAIR*160);    // 16c x 6row x 35 halo tile
    float* s_b  = s_in + 16*210;                // NCONV*16 biases

    const int tid = threadIdx.x;
    const int bt  = blockIdx.y;                 // image 0..127
    const int th0 = (blockIdx.x >> 2) * 4;      // tile origin h
    const int tw0 = (blockIdx.x & 3) * 32;      // tile origin w

    const float* x = (NCONV == 3) ? xin : g_q;  // final conv reads y (on g_q)

    const int cg  = tid >> 5;           // warp = channel group (PPG pairs)
    const int sl  = tid & 31;           // pixel slot
    const int py  = sl >> 3;            // tile row 0..3
    const int x0  = (sl & 7) * 4;       // tile col start

    // ---- prefetch input group A (ic 0..7) into regs ----
    float pf[13];
#pragma unroll
    for (int j = 0; j < 13; ++j) {
        int idx = tid + j*128;
        float v = 0.f;
        if (idx < 1632) {
            int c   = idx / 204;
            int rem = idx - c*204;
            int yy  = rem / 34;
            int xx  = rem - yy*34;
            int gh  = th0 + yy - 1;
            int gw  = tw0 + xx - 1;
            if (gh >= 0 && gh < 128 && gw >= 0 && gw < 128)
                v = x[((size_t)bt*16 + c)*HW + gh*128 + gw];
        }
        pf[j] = v;
    }

    // ---- stage weights (hides group A LDG latency) ----
    {
        const float* wsrc[3] = {w0, w1, w2};
        for (int idx = tid; idx < NPAIR*144; idx += 128) {
            int pair = idx / 144;
            int r    = idx - pair*144;          // ic*9 + j
            int chA  = pair*2, chB = chA + 1;
            float a  = wsrc[chA >> 4][(chA & 15)*144 + r];
            float b  = wsrc[chB >> 4][(chB & 15)*144 + r];
            int ic   = r / 9;
            int j    = r - ic*9;
            s_w2[(pair*16 + ic)*10 + j] = pk2(a, b);
        }
        for (int idx = tid; idx < NCONV*16; idx += 128) {
            float bv;
            if (NCONV == 3) bv = (idx < 16) ? b0[idx] : (idx < 32 ? b1[idx-16] : b2[idx-32]);
            else            bv = b0[idx];
            s_b[idx] = bv;
        }
    }

    // ---- store group A to smem ----
#pragma unroll
    for (int j = 0; j < 13; ++j) {
        int idx = tid + j*128;
        if (idx < 1632) {
            int c   = idx / 204;
            int rem = idx - c*204;
            int yy  = rem / 34;
            int xx  = rem - yy*34;
            s_in[c*210 + yy*35 + xx] = pf[j];
        }
    }
    __syncthreads();

    // ---- prefetch input group B (ic 8..15); latency hides under compute A
#pragma unroll
    for (int j = 0; j < 13; ++j) {
        int idx = tid + j*128;
        float v = 0.f;
        if (idx < 1632) {
            int c   = 8 + idx / 204;
            int rem = idx - (c - 8)*204;
            int yy  = rem / 34;
            int xx  = rem - yy*34;
            int gh  = th0 + yy - 1;
            int gw  = tw0 + xx - 1;
            if (gh >= 0 && gh < 128 && gw >= 0 && gw < 128)
                v = x[((size_t)bt*16 + c)*HW + gh*128 + gw];
        }
        pf[j] = v;
    }

    ull acc[PPG][4];
#pragma unroll
    for (int c = 0; c < PPG; ++c) {
        int q = cg*PPG + c;
        ull b2 = pk2(s_b[2*q], s_b[2*q + 1]);
#pragma unroll
        for (int p = 0; p < 4; ++p) acc[c][p] = b2;
    }

    // ---- compute halves: ic 0..7 (then store B, sync), ic 8..15 ----
#pragma unroll 1
    for (int half = 0; half < 2; ++half) {
        const int iclo = half*8;
        for (int ic = iclo; ic < iclo + 8; ++ic) {
            const float* base = s_in + ic*210 + py*35 + x0;   // rows py..py+2
            ull pkk[3][6];
#pragma unroll
            for (int ky = 0; ky < 3; ++ky)
#pragma unroll
                for (int j = 0; j < 6; ++j) {
                    float v = base[ky*35 + j];
                    pkk[ky][j] = pk2(v, v);
                }
#pragma unroll
            for (int c = 0; c < PPG; ++c) {
                const ull* wp = s_w2 + ((cg*PPG + c)*16 + ic)*10;
                ulonglong2 wA = *(const ulonglong2*)wp;        // taps 0,1
                ulonglong2 wB = *(const ulonglong2*)(wp + 2);  // taps 2,3
                ulonglong2 wC = *(const ulonglong2*)(wp + 4);  // taps 4,5
                ulonglong2 wD = *(const ulonglong2*)(wp + 6);  // taps 6,7
                ull w8 = wp[8];
#pragma unroll
                for (int px = 0; px < 4; ++px) {
                    ull a = acc[c][px];
                    fma2(a, pkk[0][px+0], wA.x);
                    fma2(a, pkk[0][px+1], wA.y);
                    fma2(a, pkk[0][px+2], wB.x);
                    fma2(a, pkk[1][px+0], wB.y);
                    fma2(a, pkk[1][px+1], wC.x);
                    fma2(a, pkk[1][px+2], wC.y);
                    fma2(a, pkk[2][px+0], wD.x);
                    fma2(a, pkk[2][px+1], wD.y);
                    fma2(a, pkk[2][px+2], w8);
                    acc[c][px] = a;
                }
            }
        }
        if (half == 0) {
            // store group B, make visible
#pragma unroll
            for (int j = 0; j < 13; ++j) {
                int idx = tid + j*128;
                if (idx < 1632) {
                    int c   = 8 + idx / 204;
                    int rem = idx - (c - 8)*204;
                    int yy  = rem / 34;
                    int xx  = rem - yy*34;
                    s_in[c*210 + yy*35 + xx] = pf[j];
                }
            }
            __syncthreads();
        }
    }

    const int oh = th0 + py;
    const int ow = tw0 + x0;
#pragma unroll
    for (int c = 0; c < PPG; ++c) {
        int q2   = cg*PPG + c;
        int chA  = 2*q2;                 // even; pair never straddles convs
        int conv = chA >> 4;
        int ocA  = chA & 15;
        size_t offA = ((size_t)bt*16 + ocA)*HW + oh*128 + ow;
        size_t offB = offA + HW;
        float2 v0 = upk(acc[c][0]);
        float2 v1 = upk(acc[c][1]);
        float2 v2 = upk(acc[c][2]);
        float2 v3 = upk(acc[c][3]);
        if (NCONV == 1) {
            *(float4*)(out_final + offA) = make_float4(v0.x, v1.x, v2.x, v3.x);
            *(float4*)(out_final + offB) = make_float4(v0.y, v1.y, v2.y, v3.y);
        } else if (conv == 2) {          // v: fp32
            *(float4*)(g_v + offA) = make_float4(v0.x, v1.x, v2.x, v3.x);
            *(float4*)(g_v + offB) = make_float4(v0.y, v1.y, v2.y, v3.y);
        } else {                          // q or k: bf16
            __nv_bfloat16* dst = (conv == 0) ? g_qh : g_kh;
            __nv_bfloat162 a0 = __floats2bfloat162_rn(v0.x, v1.x);
            __nv_bfloat162 a1 = __floats2bfloat162_rn(v2.x, v3.x);
            __nv_bfloat162 b0p = __floats2bfloat162_rn(v0.y, v1.y);
            __nv_bfloat162 b1p = __floats2bfloat162_rn(v2.y, v3.y);
            uint2 uA, uB;
            uA.x = *(unsigned*)&a0;  uA.y = *(unsigned*)&a1;
            uB.x = *(unsigned*)&b0p; uB.y = *(unsigned*)&b1p;
            *(uint2*)(dst + offA) = uA;
            *(uint2*)(dst + offB) = uB;
        }
    }
}

// ---------------- QK^T: 2-stage pipelined staging, FFMA2 inner -----------
__global__ void __launch_bounds__(256, 3) qk_kernel()
{
    extern __shared__ float sm[];       // stage stride 8704 floats
    const int bh = blockIdx.y;
    const int b  = bh >> 3, h = bh & 7;
    const int split = blockIdx.x;
    const int tid = threadIdx.x;
    const int ty = tid >> 4, tx = tid & 15;

    int st_t[4], st_kq[4];
#pragma unroll
    for (int j = 0; j < 4; ++j) {
        int i = tid + j*256;
        st_t[j]  = i >> 4;
        st_kq[j] = (i & 15) << 2;
    }

    uint2 qr[4], kr[4];
    {
        const int kc = split*512;
#pragma unroll
        for (int j = 0; j < 4; ++j) {
            size_t base = ((size_t)((b*64 + st_t[j])*16 + h*2))*HW + kc + st_kq[j];
            qr[j] = *(const uint2*)(g_qh + base);
            kr[j] = *(const uint2*)(g_kh + base);
        }
    }

    ull acc2[4][2];
#pragma unroll
    for (int i = 0; i < 4; ++i) { acc2[i][0] = 0ULL; acc2[i][1] = 0ULL; }

    for (int sub = 0; sub < 8; ++sub) {
        float* Qs = sm + (sub & 1)*8704;
        float* Ks = Qs + 4352;
        __syncthreads();
#pragma unroll
        for (int j = 0; j < 4; ++j) {
            float2 q01 = __bfloat1622float2(*(const __nv_bfloat162*)&qr[j].x);
            float2 q23 = __bfloat1622float2(*(const __nv_bfloat162*)&qr[j].y);
            float2 k01 = __bfloat1622float2(*(const __nv_bfloat162*)&kr[j].x);
            float2 k23 = __bfloat1622float2(*(const __nv_bfloat162*)&kr[j].y);
            int t = st_t[j], kq = st_kq[j];
            Qs[(kq+0)*68 + t] = q01.x; Qs[(kq+1)*68 + t] = q01.y;
            Qs[(kq+2)*68 + t] = q23.x; Qs[(kq+3)*68 + t] = q23.y;
            Ks[(kq+0)*68 + t] = k01.x; Ks[(kq+1)*68 + t] = k01.y;
            Ks[(kq+2)*68 + t] = k23.x; Ks[(kq+3)*68 + t] = k23.y;
        }
        if (sub < 7) {
            const int kc = split*512 + (sub+1)*64;
#pragma unroll
            for (int j = 0; j < 4; ++j) {
                size_t base = ((size_t)((b*64 + st_t[j])*16 + h*2))*HW + kc + st_kq[j];
                qr[j] = *(const uint2*)(g_qh + base);
                kr[j] = *(const uint2*)(g_kh + base);
            }
        }
        __syncthreads();
#pragma unroll 8
        for (int kk = 0; kk < 64; ++kk) {
            float4 a = *(const float4*)(Qs + kk*68 + ty*4);
            ulonglong2 bp = *(const ulonglong2*)(Ks + kk*68 + tx*4);
            ull a0 = pk2(a.x, a.x);
            ull a1 = pk2(a.y, a.y);
            ull a2 = pk2(a.z, a.z);
            ull a3 = pk2(a.w, a.w);
            fma2(acc2[0][0], a0, bp.x); fma2(acc2[0][1], a0, bp.y);
            fma2(acc2[1][0], a1, bp.x); fma2(acc2[1][1], a1, bp.y);
            fma2(acc2[2][0], a2, bp.x); fma2(acc2[2][1], a2, bp.y);
            fma2(acc2[3][0], a3, bp.x); fma2(acc2[3][1], a3, bp.y);
        }
    }

    float* dst = g_part + ((size_t)(split*16 + bh))*4096;
#pragma unroll
    for (int i = 0; i < 4; ++i) {
        float2 lo = upk(acc2[i][0]);
        float2 hi = upk(acc2[i][1]);
        *(float4*)(dst + (ty*4 + i)*64 + tx*4) = make_float4(lo.x, lo.y, hi.x, hi.y);
    }
}

// ---------------- split-reduce + causal softmax ----------------
__global__ void softmax_kernel()
{
    const int bh = blockIdx.y;
    const int t  = blockIdx.x;
    const int s  = threadIdx.x;

    float ssum = 0.f;
    for (int sp = 0; sp < 64; ++sp)
        ssum += g_part[((size_t)(sp*16 + bh)*64 + t)*64 + s];

    const float scale = rsqrtf(32768.0f);
    const bool valid = (s <= t);
    float logit = valid ? ssum * scale : -INFINITY;

    __shared__ float red[64];
    red[s] = logit;
    __syncthreads();
    for (int off = 32; off > 0; off >>= 1) {
        if (s < off) red[s] = fmaxf(red[s], red[s + off]);
        __syncthreads();
    }
    float mx = red[0];
    __syncthreads();
    float e = valid ? expf(logit - mx) : 0.f;
    red[s] = e;
    __syncthreads();
    for (int off = 32; off > 0; off >>= 1) {
        if (s < off) red[s] += red[s + off];
        __syncthreads();
    }
    float p = e / red[0];
    g_att[(bh*64 + s)*64 + t] = p;   // 0 for s > t
}

// ---------------- y = att @ V: 2 d/thread, MLP=4 v batching ---------------
__global__ void __launch_bounds__(256, 2) av_kernel()
{
    __shared__ __align__(16) float sa[64][32];   // att[s][t0+tt]
    const int bh = blockIdx.z;
    const int b  = bh >> 3, h = bh & 7;
    const int thalf = blockIdx.y;
    const int t0 = thalf * 32;
    const int smax = thalf ? 64 : 32;   // causal: lower t-half only needs s<32
    const int d0 = blockIdx.x*512 + threadIdx.x*2;

    for (int i = threadIdx.x; i < smax*8; i += 256) {
        int s = i >> 3; int tg = i & 7;
        *(float4*)&sa[s][tg*4] = *(const float4*)(g_att + (bh*64 + s)*64 + t0 + tg*4);
    }
    __syncthreads();

    ull acc[16][2];
#pragma unroll
    for (int g = 0; g < 16; ++g) { acc[g][0] = 0ULL; acc[g][1] = 0ULL; }

    const size_t vbase = ((size_t)(b*64*16 + h*2))*HW + d0;
    for (int s0 = 0; s0 < smax; s0 += 4) {
        float2 vv[4];
#pragma unroll
        for (int j = 0; j < 4; ++j)                 // 4 outstanding LDG.64
            vv[j] = *(const float2*)(g_v + vbase + (size_t)(s0 + j)*16*HW);
#pragma unroll
        for (int j = 0; j < 4; ++j) {
            ull va = pk2(vv[j].x, vv[j].x);
            ull vb = pk2(vv[j].y, vv[j].y);
            const int s = s0 + j;
#pragma unroll
            for (int g = 0; g < 8; ++g) {
                ulonglong2 ap = *(const ulonglong2*)&sa[s][g*4];
                fma2(acc[g*2+0][0], ap.x, va);
                fma2(acc[g*2+0][1], ap.x, vb);
                fma2(acc[g*2+1][0], ap.y, va);
                fma2(acc[g*2+1][1], ap.y, vb);
            }
        }
    }

#pragma unroll
    for (int g = 0; g < 16; ++g) {
        float2 oA = upk(acc[g][0]);   // d0 column: (t even, t odd)
        float2 oB = upk(acc[g][1]);   // d0+1 column
        int t = t0 + g*2;
        *(float2*)(g_q + ((size_t)((b*64 + t  )*16 + h*2))*HW + d0) = make_float2(oA.x, oB.x);
        *(float2*)(g_q + ((size_t)((b*64 + t+1)*16 + h*2))*HW + d0) = make_float2(oA.y, oB.y);
    }
}

// ---------------- launch ----------------
extern "C" void kernel_launch(void* const* d_in, const int* in_sizes, int n_in,
                              void* d_out, int out_size)
{
    const float* x  = (const float*)d_in[0];
    const float* wq = (const float*)d_in[1];
    const float* bq = (const float*)d_in[2];
    const float* wk = (const float*)d_in[3];
    const float* bk = (const float*)d_in[4];
    const float* wv = (const float*)d_in[5];
    const float* bv = (const float*)d_in[6];
    const float* wo = (const float*)d_in[7];
    const float* bo = (const float*)d_in[8];
    float* out = (float*)d_out;

    const int smem3 = 24*160*8 + 16*210*4 + 48*4;  // 44352 B
    const int smem1 = 8*160*8  + 16*210*4 + 16*4;  // 23744 B
    const int smemQK = 2 * 2 * 4352 * 4;           // 69632 B
    cudaFuncSetAttribute(conv3x3_kernel<3>, cudaFuncAttributeMaxDynamicSharedMemorySize, smem3);
    cudaFuncSetAttribute(conv3x3_kernel<1>, cudaFuncAttributeMaxDynamicSharedMemorySize, smem1);
    cudaFuncSetAttribute(qk_kernel, cudaFuncAttributeMaxDynamicSharedMemorySize, smemQK);

    dim3 cgrid(128, 128);   // 128 tiles (32x4) x 128 images
    conv3x3_kernel<3><<<cgrid, 128, smem3>>>(x, wq, bq, wk, bk, wv, bv, nullptr);
    qk_kernel<<<dim3(64, 16), 256, smemQK>>>();
    softmax_kernel<<<dim3(64, 16), 64>>>();
    av_kernel<<<dim3(64, 2, 16), 256>>>();
    conv3x3_kernel<1><<<cgrid, 128, smem1>>>(nullptr, wo, bo, nullptr, nullptr,
                                             nullptr, nullptr, out);
}